// round 2
// baseline (speedup 1.0000x reference)
#include <cuda_runtime.h>

// Problem constants
#define BB   4
#define SS   4096
#define DIN  768
#define HD   64
#define MM   (BB*SS)   // 16384 rows

// Scratch (device globals: allocation-free)
__device__ float g_q [MM * HD];
__device__ float g_k [MM * HD];
__device__ float g_v [MM * HD];
__device__ float g_qt[BB * HD * SS];   // [b][d][s], pre-scaled by 1/8
__device__ float g_kt[BB * HD * SS];   // [b][d][s]

// ---------------------------------------------------------------------------
// Packed fp32x2 helpers (B300 dual-FP32 pipe; ptxas never emits FFMA2 from C++)
// ---------------------------------------------------------------------------
typedef unsigned long long ull;

__device__ __forceinline__ ull dup2(float x) {
    ull r; asm("mov.b64 %0, {%1,%1};" : "=l"(r) : "f"(x)); return r;
}
__device__ __forceinline__ void fma2(ull& d, ull a, ull b) {
    asm("fma.rn.f32x2 %0, %1, %2, %0;" : "+l"(d) : "l"(a), "l"(b));
}
__device__ __forceinline__ void mul2(ull& d, ull a) {
    asm("mul.rn.f32x2 %0, %0, %1;" : "+l"(d) : "l"(a));
}
__device__ __forceinline__ void unpack2(ull v, float& x, float& y) {
    asm("mov.b64 {%0,%1}, %2;" : "=f"(x), "=f"(y) : "l"(v));
}

// ---------------------------------------------------------------------------
// Kernel 1: fused QKV projection.  out = x @ W   (M=16384, K=768, N=64)
// grid = (M/128, 3), block = 256.  Tile 128x64, BK=16, micro 8x4, FFMA2.
// ---------------------------------------------------------------------------
__global__ __launch_bounds__(256) void qkv_kernel(
    const float* __restrict__ x,
    const float* __restrict__ Wq,
    const float* __restrict__ Wk,
    const float* __restrict__ Wv)
{
    const int which = blockIdx.y;
    const float* __restrict__ W = (which == 0) ? Wq : (which == 1) ? Wk : Wv;
    float* __restrict__ out = (which == 0) ? g_q : (which == 1) ? g_k : g_v;

    const int m0 = blockIdx.x * 128;

    __shared__ float Xs[16][132];   // [k][m], padded
    __shared__ float Ws[16][68];    // [k][n], padded

    const int tid = threadIdx.x;
    const int tx = tid & 15;        // n (16 * 4 = 64)
    const int ty = tid >> 4;        // m (16 * 8 = 128)

    ull acc2[8][2];
    #pragma unroll
    for (int i = 0; i < 8; i++) { acc2[i][0] = 0ull; acc2[i][1] = 0ull; }

    for (int k0 = 0; k0 < DIN; k0 += 16) {
        #pragma unroll
        for (int r = 0; r < 2; r++) {
            int f4  = tid + r * 256;
            int row = f4 >> 2;
            int kc  = (f4 & 3) * 4;
            float4 v = *(const float4*)&x[(size_t)(m0 + row) * DIN + k0 + kc];
            Xs[kc + 0][row] = v.x;
            Xs[kc + 1][row] = v.y;
            Xs[kc + 2][row] = v.z;
            Xs[kc + 3][row] = v.w;
        }
        {
            int row = tid >> 4;
            int col = (tid & 15) * 4;
            *(float4*)&Ws[row][col] = *(const float4*)&W[(size_t)(k0 + row) * HD + col];
        }
        __syncthreads();

        #pragma unroll
        for (int kk = 0; kk < 16; kk++) {
            float4 a0 = *(const float4*)&Xs[kk][ty * 8];
            float4 a1 = *(const float4*)&Xs[kk][ty * 8 + 4];
            ulonglong2 b2 = *(const ulonglong2*)&Ws[kk][tx * 4];
            float av[8] = {a0.x, a0.y, a0.z, a0.w, a1.x, a1.y, a1.z, a1.w};
            #pragma unroll
            for (int i = 0; i < 8; i++) {
                ull ad = dup2(av[i]);
                fma2(acc2[i][0], ad, b2.x);
                fma2(acc2[i][1], ad, b2.y);
            }
        }
        __syncthreads();
    }

    #pragma unroll
    for (int i = 0; i < 8; i++) {
        float f0, f1, f2, f3;
        unpack2(acc2[i][0], f0, f1);
        unpack2(acc2[i][1], f2, f3);
        *(float4*)&out[(size_t)(m0 + ty * 8 + i) * HD + tx * 4] =
            make_float4(f0, f1, f2, f3);
    }
}

// ---------------------------------------------------------------------------
// Kernel 1b: transpose Q and K per batch into [d][s] layout.
// Q is additionally pre-scaled by 1/8 (softmax scale).
// grid = (64 s-tiles, 4 batch, 2 tensor), block = 256.
// ---------------------------------------------------------------------------
__global__ __launch_bounds__(256) void transpose_qk_kernel()
{
    const int s0 = blockIdx.x * 64;
    const int b  = blockIdx.y;
    const int t  = blockIdx.z;
    const float* __restrict__ src = (t == 0) ? g_q : g_k;
    float* __restrict__ dst       = (t == 0) ? g_qt : g_kt;
    const float scale = (t == 0) ? 0.125f : 1.0f;

    __shared__ float Ts[64][68];
    const int tid = threadIdx.x;
    const int tx = tid & 15;
    const int ty = tid >> 4;

    #pragma unroll
    for (int r = 0; r < 4; r++) {
        int f4  = tid + r * 256;
        int row = f4 >> 4;
        int dc  = (f4 & 15) * 4;
        float4 v = *(const float4*)&src[(size_t)(b * SS + s0 + row) * HD + dc];
        Ts[dc + 0][row] = v.x * scale;
        Ts[dc + 1][row] = v.y * scale;
        Ts[dc + 2][row] = v.z * scale;
        Ts[dc + 3][row] = v.w * scale;
    }
    __syncthreads();

    #pragma unroll
    for (int r = 0; r < 4; r++) {
        int d = ty + 16 * r;
        float4 o = *(const float4*)&Ts[d][tx * 4];
        *(float4*)&dst[(size_t)(b * HD + d) * SS + s0 + tx * 4] = o;
    }
}

// ---------------------------------------------------------------------------
// Kernel 2: causal flash attention, fp32 with FFMA2.
// BM = BN = 64, 256 threads, micro 4x4.
// CTA pair p handles q-tiles {p, 63-p} -> 65 key-blocks each. grid = (32, B).
// Register softmax (shfl width-16), conflict-free smem, K/V register prefetch.
// ---------------------------------------------------------------------------
#define QP 68
#define SP 65
#define SMEM_ATTN ((3 * 64 * QP + 64 * SP) * (int)sizeof(float))

__global__ __launch_bounds__(256) void attn_kernel(float* __restrict__ out)
{
    extern __shared__ float sm[];
    float (*Qs)[QP] = (float (*)[QP])(sm);
    float (*Ks)[QP] = (float (*)[QP])(sm + 64 * QP);
    float (*Vs)[QP] = (float (*)[QP])(sm + 2 * 64 * QP);
    float (*Ss)[SP] = (float (*)[SP])(sm + 3 * 64 * QP);

    const int b   = blockIdx.y;
    const int p   = blockIdx.x;          // 0..31
    const int tid = threadIdx.x;
    const int tx  = tid & 15;            // n / c dimension (4 each)
    const int ty  = tid >> 4;            // m dimension (4 each)

    const float* __restrict__ qt = g_qt + (size_t)b * HD * SS;
    const float* __restrict__ kt = g_kt + (size_t)b * HD * SS;
    const float* __restrict__ vb = g_v  + (size_t)b * SS * HD;

    #pragma unroll 1
    for (int half = 0; half < 2; half++) {
        const int qi = (half == 0) ? p : (63 - p);

        // ---- load Q tile (already [d][s] in gmem; conflict-free f4 both ways)
        #pragma unroll
        for (int r = 0; r < 4; r++) {
            int d = ty + 16 * r;
            float4 v = *(const float4*)&qt[(size_t)d * SS + qi * 64 + tx * 4];
            *(float4*)&Qs[d][tx * 4] = v;
        }

        ull o2[4][2];
        float mprev[4], lprev[4];
        #pragma unroll
        for (int i = 0; i < 4; i++) {
            o2[i][0] = 0ull; o2[i][1] = 0ull;
            mprev[i] = -1e30f; lprev[i] = 0.f;
        }

        // ---- prefetch kb=0 K,V into registers ----
        float4 kreg[4], vreg[4];
        #pragma unroll
        for (int r = 0; r < 4; r++) {
            int d = ty + 16 * r;
            kreg[r] = *(const float4*)&kt[(size_t)d * SS + tx * 4];
            vreg[r] = *(const float4*)&vb[(size_t)(ty + 16 * r) * HD + tx * 4];
        }
        __syncthreads();   // Qs visible; prior half's smem readers done

        for (int kb = 0; kb <= qi; kb++) {
            // ---- commit prefetched K,V to smem (conflict-free float4) ----
            #pragma unroll
            for (int r = 0; r < 4; r++) {
                *(float4*)&Ks[ty + 16 * r][tx * 4] = kreg[r];
                *(float4*)&Vs[ty + 16 * r][tx * 4] = vreg[r];
            }
            __syncthreads();

            // ---- prefetch next K,V (hidden under compute) ----
            if (kb < qi) {
                #pragma unroll
                for (int r = 0; r < 4; r++) {
                    int d = ty + 16 * r;
                    kreg[r] = *(const float4*)&kt[(size_t)d * SS + (kb + 1) * 64 + tx * 4];
                    vreg[r] = *(const float4*)&vb[(size_t)((kb + 1) * 64 + ty + 16 * r) * HD + tx * 4];
                }
            }

            // ---- S = Q K^T (Q pre-scaled), FFMA2 ----
            ull s2[4][2];
            #pragma unroll
            for (int i = 0; i < 4; i++) { s2[i][0] = 0ull; s2[i][1] = 0ull; }

            #pragma unroll 16
            for (int d = 0; d < HD; d++) {
                float4 qa = *(const float4*)&Qs[d][ty * 4];
                ulonglong2 k2 = *(const ulonglong2*)&Ks[d][tx * 4];
                float qv[4] = {qa.x, qa.y, qa.z, qa.w};
                #pragma unroll
                for (int i = 0; i < 4; i++) {
                    ull ad = dup2(qv[i]);
                    fma2(s2[i][0], ad, k2.x);
                    fma2(s2[i][1], ad, k2.y);
                }
            }

            float s[4][4];
            #pragma unroll
            for (int i = 0; i < 4; i++) {
                unpack2(s2[i][0], s[i][0], s[i][1]);
                unpack2(s2[i][1], s[i][2], s[i][3]);
            }

            // causal mask on diagonal block
            if (kb == qi) {
                #pragma unroll
                for (int i = 0; i < 4; i++)
                    #pragma unroll
                    for (int j = 0; j < 4; j++)
                        if (tx * 4 + j > ty * 4 + i) s[i][j] = -1e30f;
            }

            // ---- register online softmax (row groups = lanes 0-15 / 16-31) ----
            #pragma unroll
            for (int i = 0; i < 4; i++) {
                float mx = fmaxf(fmaxf(s[i][0], s[i][1]), fmaxf(s[i][2], s[i][3]));
                #pragma unroll
                for (int w = 1; w < 16; w <<= 1)
                    mx = fmaxf(mx, __shfl_xor_sync(0xffffffffu, mx, w));
                float mnew = fmaxf(mprev[i], mx);
                float corr = __expf(mprev[i] - mnew);
                float p0 = __expf(s[i][0] - mnew);
                float p1 = __expf(s[i][1] - mnew);
                float p2 = __expf(s[i][2] - mnew);
                float p3 = __expf(s[i][3] - mnew);
                float sum = (p0 + p1) + (p2 + p3);
                #pragma unroll
                for (int w = 1; w < 16; w <<= 1)
                    sum += __shfl_xor_sync(0xffffffffu, sum, w);
                lprev[i] = lprev[i] * corr + sum;
                mprev[i] = mnew;
                ull c2 = dup2(corr);
                mul2(o2[i][0], c2);
                mul2(o2[i][1], c2);
                int m = ty * 4 + i;
                Ss[m][tx * 4 + 0] = p0;
                Ss[m][tx * 4 + 1] = p1;
                Ss[m][tx * 4 + 2] = p2;
                Ss[m][tx * 4 + 3] = p3;
            }
            __syncthreads();

            // ---- O += P @ V, FFMA2 (P broadcast loads, V vector loads) ----
            #pragma unroll 16
            for (int n = 0; n < 64; n++) {
                ulonglong2 v2 = *(const ulonglong2*)&Vs[n][tx * 4];
                #pragma unroll
                for (int i = 0; i < 4; i++) {
                    ull pd = dup2(Ss[ty * 4 + i][n]);
                    fma2(o2[i][0], pd, v2.x);
                    fma2(o2[i][1], pd, v2.y);
                }
            }
            __syncthreads();   // protect Ks/Vs/Ss before next iteration
        }

        // ---- normalize and write out ----
        #pragma unroll
        for (int i = 0; i < 4; i++) {
            float f0, f1, f2, f3;
            unpack2(o2[i][0], f0, f1);
            unpack2(o2[i][1], f2, f3);
            float linv = 1.0f / lprev[i];
            int m = qi * 64 + ty * 4 + i;
            *(float4*)&out[((size_t)b * SS + m) * HD + tx * 4] =
                make_float4(f0 * linv, f1 * linv, f2 * linv, f3 * linv);
        }
    }
}

// ---------------------------------------------------------------------------
// kernel_launch
// ---------------------------------------------------------------------------
extern "C" void kernel_launch(void* const* d_in, const int* in_sizes, int n_in,
                              void* d_out, int out_size)
{
    const float* x  = (const float*)d_in[0];
    const float* Wq = (const float*)d_in[1];
    const float* Wk = (const float*)d_in[2];
    const float* Wv = (const float*)d_in[3];
    float* out = (float*)d_out;

    static int smem_set = 0;
    if (!smem_set) {
        cudaFuncSetAttribute(attn_kernel,
                             cudaFuncAttributeMaxDynamicSharedMemorySize,
                             SMEM_ATTN);
        smem_set = 1;
    }

    dim3 g1(MM / 128, 3);
    qkv_kernel<<<g1, 256>>>(x, Wq, Wk, Wv);

    dim3 gt(64, BB, 2);
    transpose_qk_kernel<<<gt, 256>>>();

    dim3 g2(32, BB);
    attn_kernel<<<g2, 256, SMEM_ATTN>>>(out);
}

// round 4
// speedup vs baseline: 3.3768x; 3.3768x over previous
#include <cuda_runtime.h>

// Problem constants
#define BB   4
#define SS   4096
#define DIN  768
#define HD   64
#define MM   (BB*SS)   // 16384 rows

// Scratch for Q, K, V projections (device globals: allocation-free)
__device__ float g_q[MM * HD];
__device__ float g_k[MM * HD];
__device__ float g_v[MM * HD];

// ---------------------------------------------------------------------------
// tf32 helpers
// ---------------------------------------------------------------------------
__device__ __forceinline__ unsigned f2tf(float f) {
    unsigned u;
    asm("cvt.rna.tf32.f32 %0, %1;" : "=r"(u) : "f"(f));
    return u;
}
__device__ __forceinline__ uint4 f2tf4(float4 v) {
    uint4 t;
    t.x = f2tf(v.x); t.y = f2tf(v.y); t.z = f2tf(v.z); t.w = f2tf(v.w);
    return t;
}
// D = A(m16 x k8, row) * B(k8 x n8, col) + D   (tf32 in, f32 accum)
__device__ __forceinline__ void mma8(float* c, const unsigned* a,
                                     unsigned b0, unsigned b1) {
    asm("mma.sync.aligned.m16n8k8.row.col.f32.tf32.tf32.f32 "
        "{%0,%1,%2,%3},{%4,%5,%6,%7},{%8,%9},{%0,%1,%2,%3};"
        : "+f"(c[0]), "+f"(c[1]), "+f"(c[2]), "+f"(c[3])
        : "r"(a[0]), "r"(a[1]), "r"(a[2]), "r"(a[3]), "r"(b0), "r"(b1));
}

// ---------------------------------------------------------------------------
// Kernel 1: fused QKV projection (single pass over x).
// out{q,k,v} = x @ W{q,k,v}   (M=16384, K=768, N=64 each -> N=192 fused)
// grid = 128, block = 256 (8 warps, each m16 x n192).  BK = 32.
// ---------------------------------------------------------------------------
__global__ __launch_bounds__(256) void qkv_kernel(
    const float* __restrict__ x,
    const float* __restrict__ Wq,
    const float* __restrict__ Wk,
    const float* __restrict__ Wv)
{
    __shared__ unsigned Xs[128][36];    // [m][k] tf32, pad 36 (bank=lane on A loads)
    __shared__ unsigned Ws[32][200];    // [k][n=192] tf32, pad 200 (8*lr+lq distinct)

    const int tid  = threadIdx.x;
    const int lane = tid & 31;
    const int warp = tid >> 5;
    const int lq = lane >> 2;           // groupID (row group)
    const int lr = lane & 3;            // threadID_in_group
    const int wm = warp * 16;
    const int m0 = blockIdx.x * 128;

    float c[24][4];
    #pragma unroll
    for (int nf = 0; nf < 24; nf++)
        #pragma unroll
        for (int j = 0; j < 4; j++) c[nf][j] = 0.f;

    float4 xreg[4], wreg[6];

    // prefetch chunk k0=0
    #pragma unroll
    for (int r = 0; r < 4; r++) {
        int idx = tid + r * 256;              // 0..1023
        int row = idx >> 3, c4 = (idx & 7) * 4;
        xreg[r] = *(const float4*)&x[(size_t)(m0 + row) * DIN + c4];
    }
    #pragma unroll
    for (int r = 0; r < 6; r++) {
        int idx = tid + r * 256;              // 0..1535
        int wsel = idx >> 9;
        int j = idx & 511;
        int row = j >> 4, c4 = (j & 15) * 4;
        const float* W = (wsel == 0) ? Wq : (wsel == 1) ? Wk : Wv;
        wreg[r] = *(const float4*)&W[(size_t)row * HD + c4];
    }

    for (int k0 = 0; k0 < DIN; k0 += 32) {
        // commit staged tiles (cvt to tf32)
        #pragma unroll
        for (int r = 0; r < 4; r++) {
            int idx = tid + r * 256;
            int row = idx >> 3, c4 = (idx & 7) * 4;
            *(uint4*)&Xs[row][c4] = f2tf4(xreg[r]);
        }
        #pragma unroll
        for (int r = 0; r < 6; r++) {
            int idx = tid + r * 256;
            int wsel = idx >> 9;
            int j = idx & 511;
            int row = j >> 4, c4 = (j & 15) * 4;
            *(uint4*)&Ws[row][wsel * 64 + c4] = f2tf4(wreg[r]);
        }
        __syncthreads();

        // prefetch next chunk
        if (k0 + 32 < DIN) {
            #pragma unroll
            for (int r = 0; r < 4; r++) {
                int idx = tid + r * 256;
                int row = idx >> 3, c4 = (idx & 7) * 4;
                xreg[r] = *(const float4*)&x[(size_t)(m0 + row) * DIN + k0 + 32 + c4];
            }
            #pragma unroll
            for (int r = 0; r < 6; r++) {
                int idx = tid + r * 256;
                int wsel = idx >> 9;
                int j = idx & 511;
                int row = j >> 4, c4 = (j & 15) * 4;
                const float* W = (wsel == 0) ? Wq : (wsel == 1) ? Wk : Wv;
                wreg[r] = *(const float4*)&W[(size_t)(k0 + 32 + row) * HD + c4];
            }
        }

        // compute: 4 k-frags x 24 n-frags
        #pragma unroll
        for (int kf = 0; kf < 4; kf++) {
            unsigned a[4];
            a[0] = Xs[wm + lq][kf * 8 + lr];
            a[1] = Xs[wm + lq + 8][kf * 8 + lr];
            a[2] = Xs[wm + lq][kf * 8 + 4 + lr];
            a[3] = Xs[wm + lq + 8][kf * 8 + 4 + lr];
            #pragma unroll
            for (int nf = 0; nf < 24; nf++) {
                unsigned b0 = Ws[kf * 8 + lr][nf * 8 + lq];
                unsigned b1 = Ws[kf * 8 + 4 + lr][nf * 8 + lq];
                mma8(c[nf], a, b0, b1);
            }
        }
        __syncthreads();
    }

    // epilogue: c0,c1 -> (row, 2*lr..), c2,c3 -> (row+8)
    #pragma unroll
    for (int nf = 0; nf < 24; nf++) {
        int which = nf >> 3;
        int nc = (nf & 7) * 8 + 2 * lr;
        float* outp = (which == 0) ? g_q : (which == 1) ? g_k : g_v;
        *(float2*)&outp[(size_t)(m0 + wm + lq) * HD + nc] =
            make_float2(c[nf][0], c[nf][1]);
        *(float2*)&outp[(size_t)(m0 + wm + lq + 8) * HD + nc] =
            make_float2(c[nf][2], c[nf][3]);
    }
}

// ---------------------------------------------------------------------------
// Kernel 2: causal flash attention, tf32 mma.
// 128 threads (4 warps), BM = BN = 64, each warp: m16 x full n64.
// grid = (64, B), qi = 63 - blockIdx.x (big tiles first), 2 CTAs/SM.
// smem (uints): Ks[2][64][68] | Vs[2][64][72] | Ps[64][68] (also Q staging)
// ---------------------------------------------------------------------------
#define KS_W 68
#define VS_W 72
#define PS_W 68
#define KS_SZ (64 * KS_W)
#define VS_SZ (64 * VS_W)
#define SMEM_ATTN ((2 * KS_SZ + 2 * VS_SZ + 64 * PS_W) * (int)sizeof(unsigned))

__global__ __launch_bounds__(128, 2) void attn_kernel(float* __restrict__ out)
{
    extern __shared__ unsigned smu[];
    unsigned* Ks = smu;                          // [2][64][68]
    unsigned* Vs = smu + 2 * KS_SZ;              // [2][64][72]
    unsigned* Ps = smu + 2 * KS_SZ + 2 * VS_SZ;  // [64][68]

    const int b    = blockIdx.y;
    const int qi   = 63 - blockIdx.x;            // large tiles launch first
    const int tid  = threadIdx.x;
    const int lane = tid & 31;
    const int warp = tid >> 5;
    const int lq = lane >> 2;
    const int lr = lane & 3;
    const int wm = warp * 16;

    const float* __restrict__ qb = g_q + ((size_t)b * SS + qi * 64) * HD;
    const float* __restrict__ kg = g_k + (size_t)b * SS * HD;
    const float* __restrict__ vg = g_v + (size_t)b * SS * HD;

    // ---- stage Q (scaled 1/8, tf32) through Ps, build A fragments ----
    #pragma unroll
    for (int r = 0; r < 8; r++) {
        int idx = tid + r * 128;                 // 0..1023
        int row = idx >> 4, c4 = (idx & 15) * 4;
        float4 v = *(const float4*)&qb[(size_t)row * HD + c4];
        uint4 t;
        t.x = f2tf(v.x * 0.125f); t.y = f2tf(v.y * 0.125f);
        t.z = f2tf(v.z * 0.125f); t.w = f2tf(v.w * 0.125f);
        *(uint4*)&Ps[row * PS_W + c4] = t;
    }
    __syncthreads();

    unsigned aq[8][4];
    #pragma unroll
    for (int kf = 0; kf < 8; kf++) {
        aq[kf][0] = Ps[(wm + lq) * PS_W + kf * 8 + lr];
        aq[kf][1] = Ps[(wm + lq + 8) * PS_W + kf * 8 + lr];
        aq[kf][2] = Ps[(wm + lq) * PS_W + kf * 8 + 4 + lr];
        aq[kf][3] = Ps[(wm + lq + 8) * PS_W + kf * 8 + 4 + lr];
    }

    // stats + output accumulators
    float m0 = -1e30f, m1 = -1e30f, l0 = 0.f, l1 = 0.f;
    float o[8][4];
    #pragma unroll
    for (int nf = 0; nf < 8; nf++)
        #pragma unroll
        for (int j = 0; j < 4; j++) o[nf][j] = 0.f;

    // ---- prefetch K,V block 0 into registers ----
    float4 kreg[8], vreg[8];
    #pragma unroll
    for (int r = 0; r < 8; r++) {
        int idx = tid + r * 128;
        int row = idx >> 4, c4 = (idx & 15) * 4;
        kreg[r] = *(const float4*)&kg[(size_t)row * HD + c4];
        vreg[r] = *(const float4*)&vg[(size_t)row * HD + c4];
    }

    for (int kb = 0; kb <= qi; kb++) {
        unsigned* Kb = Ks + (kb & 1) * KS_SZ;
        unsigned* Vb = Vs + (kb & 1) * VS_SZ;

        // commit staged K/V (tf32)
        #pragma unroll
        for (int r = 0; r < 8; r++) {
            int idx = tid + r * 128;
            int row = idx >> 4, c4 = (idx & 15) * 4;
            *(uint4*)&Kb[row * KS_W + c4] = f2tf4(kreg[r]);
            *(uint4*)&Vb[row * VS_W + c4] = f2tf4(vreg[r]);
        }
        __syncthreads();

        // prefetch next block (hidden under compute)
        if (kb < qi) {
            #pragma unroll
            for (int r = 0; r < 8; r++) {
                int idx = tid + r * 128;
                int row = idx >> 4, c4 = (idx & 15) * 4;
                kreg[r] = *(const float4*)&kg[((size_t)(kb + 1) * 64 + row) * HD + c4];
                vreg[r] = *(const float4*)&vg[((size_t)(kb + 1) * 64 + row) * HD + c4];
            }
        }

        // ---- S = Q K^T  (m16 x n64, k=64) ----
        float s[8][4];
        #pragma unroll
        for (int nf = 0; nf < 8; nf++)
            #pragma unroll
            for (int j = 0; j < 4; j++) s[nf][j] = 0.f;

        #pragma unroll
        for (int kf = 0; kf < 8; kf++) {
            #pragma unroll
            for (int nf = 0; nf < 8; nf++) {
                unsigned b0 = Kb[(nf * 8 + lq) * KS_W + kf * 8 + lr];
                unsigned b1 = Kb[(nf * 8 + lq) * KS_W + kf * 8 + 4 + lr];
                mma8(s[nf], aq[kf], b0, b1);
            }
        }

        // ---- causal mask on diagonal block ----
        if (kb == qi) {
            int r0 = wm + lq, r1 = r0 + 8;
            #pragma unroll
            for (int nf = 0; nf < 8; nf++) {
                int cc = nf * 8 + 2 * lr;
                if (cc     > r0) s[nf][0] = -1e30f;
                if (cc + 1 > r0) s[nf][1] = -1e30f;
                if (cc     > r1) s[nf][2] = -1e30f;
                if (cc + 1 > r1) s[nf][3] = -1e30f;
            }
        }

        // ---- online softmax (rows wm+lq and wm+lq+8; quad reduce) ----
        float mx0 = -1e30f, mx1 = -1e30f;
        #pragma unroll
        for (int nf = 0; nf < 8; nf++) {
            mx0 = fmaxf(mx0, fmaxf(s[nf][0], s[nf][1]));
            mx1 = fmaxf(mx1, fmaxf(s[nf][2], s[nf][3]));
        }
        mx0 = fmaxf(mx0, __shfl_xor_sync(0xffffffffu, mx0, 1));
        mx0 = fmaxf(mx0, __shfl_xor_sync(0xffffffffu, mx0, 2));
        mx1 = fmaxf(mx1, __shfl_xor_sync(0xffffffffu, mx1, 1));
        mx1 = fmaxf(mx1, __shfl_xor_sync(0xffffffffu, mx1, 2));

        float mn0 = fmaxf(m0, mx0), mn1 = fmaxf(m1, mx1);
        float corr0 = __expf(m0 - mn0), corr1 = __expf(m1 - mn1);

        float sum0 = 0.f, sum1 = 0.f;
        #pragma unroll
        for (int nf = 0; nf < 8; nf++) {
            s[nf][0] = __expf(s[nf][0] - mn0);
            s[nf][1] = __expf(s[nf][1] - mn0);
            s[nf][2] = __expf(s[nf][2] - mn1);
            s[nf][3] = __expf(s[nf][3] - mn1);
            sum0 += s[nf][0] + s[nf][1];
            sum1 += s[nf][2] + s[nf][3];
        }
        sum0 += __shfl_xor_sync(0xffffffffu, sum0, 1);
        sum0 += __shfl_xor_sync(0xffffffffu, sum0, 2);
        sum1 += __shfl_xor_sync(0xffffffffu, sum1, 1);
        sum1 += __shfl_xor_sync(0xffffffffu, sum1, 2);

        l0 = l0 * corr0 + sum0;  m0 = mn0;
        l1 = l1 * corr1 + sum1;  m1 = mn1;

        #pragma unroll
        for (int nf = 0; nf < 8; nf++) {
            o[nf][0] *= corr0; o[nf][1] *= corr0;
            o[nf][2] *= corr1; o[nf][3] *= corr1;
        }

        // ---- P -> smem (warp-private rows), rebuild as A fragments ----
        #pragma unroll
        for (int nf = 0; nf < 8; nf++) {
            uint2 w0 = make_uint2(f2tf(s[nf][0]), f2tf(s[nf][1]));
            uint2 w1 = make_uint2(f2tf(s[nf][2]), f2tf(s[nf][3]));
            *(uint2*)&Ps[(wm + lq) * PS_W + nf * 8 + 2 * lr] = w0;
            *(uint2*)&Ps[(wm + lq + 8) * PS_W + nf * 8 + 2 * lr] = w1;
        }
        __syncwarp();

        // ---- O += P V  (m16 x n(d)=64, k=64 keys) ----
        #pragma unroll
        for (int kf = 0; kf < 8; kf++) {
            unsigned ap[4];
            ap[0] = Ps[(wm + lq) * PS_W + kf * 8 + lr];
            ap[1] = Ps[(wm + lq + 8) * PS_W + kf * 8 + lr];
            ap[2] = Ps[(wm + lq) * PS_W + kf * 8 + 4 + lr];
            ap[3] = Ps[(wm + lq + 8) * PS_W + kf * 8 + 4 + lr];
            #pragma unroll
            for (int nf = 0; nf < 8; nf++) {
                unsigned b0 = Vb[(kf * 8 + lr) * VS_W + nf * 8 + lq];
                unsigned b1 = Vb[(kf * 8 + 4 + lr) * VS_W + nf * 8 + lq];
                mma8(o[nf], ap, b0, b1);
            }
        }
        // no trailing barrier: next iteration writes the other K/V buffer,
        // and its top barrier orders those writes vs. this buffer's readers.
    }

    // ---- normalize + write out ----
    float il0 = 1.f / l0, il1 = 1.f / l1;
    #pragma unroll
    for (int nf = 0; nf < 8; nf++) {
        int cc = nf * 8 + 2 * lr;
        *(float2*)&out[((size_t)b * SS + qi * 64 + wm + lq) * HD + cc] =
            make_float2(o[nf][0] * il0, o[nf][1] * il0);
        *(float2*)&out[((size_t)b * SS + qi * 64 + wm + lq + 8) * HD + cc] =
            make_float2(o[nf][2] * il1, o[nf][3] * il1);
    }
}

// ---------------------------------------------------------------------------
// kernel_launch
// ---------------------------------------------------------------------------
extern "C" void kernel_launch(void* const* d_in, const int* in_sizes, int n_in,
                              void* d_out, int out_size)
{
    const float* x  = (const float*)d_in[0];
    const float* Wq = (const float*)d_in[1];
    const float* Wk = (const float*)d_in[2];
    const float* Wv = (const float*)d_in[3];
    float* out = (float*)d_out;

    static int smem_set = 0;
    if (!smem_set) {
        cudaFuncSetAttribute(attn_kernel,
                             cudaFuncAttributeMaxDynamicSharedMemorySize,
                             SMEM_ATTN);
        smem_set = 1;
    }

    qkv_kernel<<<MM / 128, 256>>>(x, Wq, Wk, Wv);

    dim3 g2(64, BB);
    attn_kernel<<<g2, 128, SMEM_ATTN>>>(out);
}

// round 7
// speedup vs baseline: 3.6251x; 1.0735x over previous
#include <cuda_runtime.h>

// Problem constants
#define BB   4
#define SS   4096
#define DIN  768
#define HD   64
#define MM   (BB*SS)   // 16384 rows

// Scratch for Q, K, V projections (device globals: allocation-free)
__device__ float g_q[MM * HD];
__device__ float g_k[MM * HD];
__device__ float g_v[MM * HD];

// ---------------------------------------------------------------------------
// tf32 helpers
// ---------------------------------------------------------------------------
__device__ __forceinline__ unsigned f2tf(float f) {
    unsigned u;
    asm("cvt.rna.tf32.f32 %0, %1;" : "=r"(u) : "f"(f));
    return u;
}
__device__ __forceinline__ uint4 f2tf4(float4 v) {
    uint4 t;
    t.x = f2tf(v.x); t.y = f2tf(v.y); t.z = f2tf(v.z); t.w = f2tf(v.w);
    return t;
}
// D = A(m16 x k8, row) * B(k8 x n8, col) + D   (tf32 in, f32 accum)
__device__ __forceinline__ void mma8(float* c, const unsigned* a,
                                     unsigned b0, unsigned b1) {
    asm("mma.sync.aligned.m16n8k8.row.col.f32.tf32.tf32.f32 "
        "{%0,%1,%2,%3},{%4,%5,%6,%7},{%8,%9},{%0,%1,%2,%3};"
        : "+f"(c[0]), "+f"(c[1]), "+f"(c[2]), "+f"(c[3])
        : "r"(a[0]), "r"(a[1]), "r"(a[2]), "r"(a[3]), "r"(b0), "r"(b1));
}
// cp.async 16B
__device__ __forceinline__ void cpa16(unsigned smem_dst, const void* gsrc) {
    asm volatile("cp.async.cg.shared.global [%0], [%1], 16;"
                 :: "r"(smem_dst), "l"(gsrc));
}
__device__ __forceinline__ void cpa_commit() {
    asm volatile("cp.async.commit_group;");
}
__device__ __forceinline__ void cpa_wait0() {
    asm volatile("cp.async.wait_group 0;");
}

// ---------------------------------------------------------------------------
// Kernel 1: fused QKV projection (single pass over x).
// out{q,k,v} = x @ W{q,k,v}   (M=16384, K=768, N=64 each -> N=192 fused)
// grid = 128, block = 256 (8 warps, each m16 x n192).  BK = 32.
// ---------------------------------------------------------------------------
__global__ __launch_bounds__(256) void qkv_kernel(
    const float* __restrict__ x,
    const float* __restrict__ Wq,
    const float* __restrict__ Wk,
    const float* __restrict__ Wv)
{
    __shared__ unsigned Xs[128][36];    // [m][k] tf32
    __shared__ unsigned Ws[32][200];    // [k][n=192] tf32

    const int tid  = threadIdx.x;
    const int lane = tid & 31;
    const int warp = tid >> 5;
    const int lq = lane >> 2;
    const int lr = lane & 3;
    const int wm = warp * 16;
    const int m0 = blockIdx.x * 128;

    float c[24][4];
    #pragma unroll
    for (int nf = 0; nf < 24; nf++)
        #pragma unroll
        for (int j = 0; j < 4; j++) c[nf][j] = 0.f;

    float4 xreg[4], wreg[6];

    #pragma unroll
    for (int r = 0; r < 4; r++) {
        int idx = tid + r * 256;
        int row = idx >> 3, c4 = (idx & 7) * 4;
        xreg[r] = *(const float4*)&x[(size_t)(m0 + row) * DIN + c4];
    }
    #pragma unroll
    for (int r = 0; r < 6; r++) {
        int idx = tid + r * 256;
        int wsel = idx >> 9;
        int j = idx & 511;
        int row = j >> 4, c4 = (j & 15) * 4;
        const float* W = (wsel == 0) ? Wq : (wsel == 1) ? Wk : Wv;
        wreg[r] = *(const float4*)&W[(size_t)row * HD + c4];
    }

    for (int k0 = 0; k0 < DIN; k0 += 32) {
        #pragma unroll
        for (int r = 0; r < 4; r++) {
            int idx = tid + r * 256;
            int row = idx >> 3, c4 = (idx & 7) * 4;
            *(uint4*)&Xs[row][c4] = f2tf4(xreg[r]);
        }
        #pragma unroll
        for (int r = 0; r < 6; r++) {
            int idx = tid + r * 256;
            int wsel = idx >> 9;
            int j = idx & 511;
            int row = j >> 4, c4 = (j & 15) * 4;
            *(uint4*)&Ws[row][wsel * 64 + c4] = f2tf4(wreg[r]);
        }
        __syncthreads();

        if (k0 + 32 < DIN) {
            #pragma unroll
            for (int r = 0; r < 4; r++) {
                int idx = tid + r * 256;
                int row = idx >> 3, c4 = (idx & 7) * 4;
                xreg[r] = *(const float4*)&x[(size_t)(m0 + row) * DIN + k0 + 32 + c4];
            }
            #pragma unroll
            for (int r = 0; r < 6; r++) {
                int idx = tid + r * 256;
                int wsel = idx >> 9;
                int j = idx & 511;
                int row = j >> 4, c4 = (j & 15) * 4;
                const float* W = (wsel == 0) ? Wq : (wsel == 1) ? Wk : Wv;
                wreg[r] = *(const float4*)&W[(size_t)(k0 + 32 + row) * HD + c4];
            }
        }

        #pragma unroll
        for (int kf = 0; kf < 4; kf++) {
            unsigned a[4];
            a[0] = Xs[wm + lq][kf * 8 + lr];
            a[1] = Xs[wm + lq + 8][kf * 8 + lr];
            a[2] = Xs[wm + lq][kf * 8 + 4 + lr];
            a[3] = Xs[wm + lq + 8][kf * 8 + 4 + lr];
            #pragma unroll
            for (int nf = 0; nf < 24; nf++) {
                unsigned b0 = Ws[kf * 8 + lr][nf * 8 + lq];
                unsigned b1 = Ws[kf * 8 + 4 + lr][nf * 8 + lq];
                mma8(c[nf], a, b0, b1);
            }
        }
        __syncthreads();
    }

    #pragma unroll
    for (int nf = 0; nf < 24; nf++) {
        int which = nf >> 3;
        int nc = (nf & 7) * 8 + 2 * lr;
        float* outp = (which == 0) ? g_q : (which == 1) ? g_k : g_v;
        *(float2*)&outp[(size_t)(m0 + wm + lq) * HD + nc] =
            make_float2(c[nf][0], c[nf][1]);
        *(float2*)&outp[(size_t)(m0 + wm + lq + 8) * HD + nc] =
            make_float2(c[nf][2], c[nf][3]);
    }
}

// ---------------------------------------------------------------------------
// Kernel 2: causal flash attention, tf32 mma + cp.async.
// 128 threads (4 warps), BM = BN = 64, each warp: m16 x full n64.
// grid = (64, B), qi = 63 - blockIdx.x, 3 CTAs/SM.
// smem (uints): Ks[64][68] (single) | Vs[2][64][72] | Ps[64][68]
// K/V kept as RAW fp32 in smem (tf32 mma truncates); Q and P use cvt.rna.
// ---------------------------------------------------------------------------
#define KS_W 68
#define VS_W 72
#define PS_W 68
#define KS_SZ (64 * KS_W)
#define VS_SZ (64 * VS_W)
#define SMEM_ATTN ((KS_SZ + 2 * VS_SZ + 64 * PS_W) * (int)sizeof(unsigned))

__global__ __launch_bounds__(128, 3) void attn_kernel(float* __restrict__ out)
{
    extern __shared__ unsigned smu[];
    unsigned* Ks = smu;                      // [64][68]
    unsigned* Vs = smu + KS_SZ;              // [2][64][72]
    unsigned* Ps = smu + KS_SZ + 2 * VS_SZ;  // [64][68]

    const int b    = blockIdx.y;
    const int qi   = 63 - blockIdx.x;        // large tiles launch first
    const int tid  = threadIdx.x;
    const int lane = tid & 31;
    const int warp = tid >> 5;
    const int lq = lane >> 2;
    const int lr = lane & 3;
    const int wm = warp * 16;

    const float* __restrict__ qb = g_q + ((size_t)b * SS + qi * 64) * HD;
    const float* __restrict__ kg = g_k + (size_t)b * SS * HD;
    const float* __restrict__ vg = g_v + (size_t)b * SS * HD;

    // per-thread load slots: idx = tid + r*128 -> row = idx>>4, c4 = (idx&15)*4
    unsigned kdst[8], vdst0[8], vdst1[8];
    size_t goff[8];
    #pragma unroll
    for (int r = 0; r < 8; r++) {
        int idx = tid + r * 128;
        int row = idx >> 4, c4 = (idx & 15) * 4;
        kdst[r]  = (unsigned)__cvta_generic_to_shared(&Ks[row * KS_W + c4]);
        vdst0[r] = (unsigned)__cvta_generic_to_shared(&Vs[row * VS_W + c4]);
        vdst1[r] = (unsigned)__cvta_generic_to_shared(&Vs[VS_SZ + row * VS_W + c4]);
        goff[r]  = (size_t)row * HD + c4;
    }

    // ---- issue K0, V0 loads (overlap with Q staging) ----
    #pragma unroll
    for (int r = 0; r < 8; r++) {
        cpa16(kdst[r],  kg + goff[r]);
        cpa16(vdst0[r], vg + goff[r]);
    }
    cpa_commit();

    // ---- stage Q (scaled 1/8, tf32) through Ps, build A fragments ----
    #pragma unroll
    for (int r = 0; r < 8; r++) {
        int idx = tid + r * 128;
        int row = idx >> 4, c4 = (idx & 15) * 4;
        float4 v = *(const float4*)&qb[(size_t)row * HD + c4];
        uint4 t;
        t.x = f2tf(v.x * 0.125f); t.y = f2tf(v.y * 0.125f);
        t.z = f2tf(v.z * 0.125f); t.w = f2tf(v.w * 0.125f);
        *(uint4*)&Ps[row * PS_W + c4] = t;
    }
    __syncthreads();

    unsigned aq[8][4];
    #pragma unroll
    for (int kf = 0; kf < 8; kf++) {
        aq[kf][0] = Ps[(wm + lq) * PS_W + kf * 8 + lr];
        aq[kf][1] = Ps[(wm + lq + 8) * PS_W + kf * 8 + lr];
        aq[kf][2] = Ps[(wm + lq) * PS_W + kf * 8 + 4 + lr];
        aq[kf][3] = Ps[(wm + lq + 8) * PS_W + kf * 8 + 4 + lr];
    }

    float m0 = -1e30f, m1 = -1e30f, l0 = 0.f, l1 = 0.f;
    float o[8][4];
    #pragma unroll
    for (int nf = 0; nf < 8; nf++)
        #pragma unroll
        for (int j = 0; j < 4; j++) o[nf][j] = 0.f;

    cpa_wait0();
    __syncthreads();          // K0,V0 visible; Q frags built in all warps

    for (int kb = 0; kb <= qi; kb++) {
        const int par = kb & 1;
        unsigned* Vb = Vs + par * VS_SZ;

        // ---- issue V_{kb+1} (into other buffer; covered by whole iter) ----
        if (kb < qi) {
            const float* vsrc = vg + (size_t)(kb + 1) * 64 * HD;
            unsigned* vd = par ? vdst0 : vdst1;
            #pragma unroll
            for (int r = 0; r < 8; r++) cpa16(vd[r], vsrc + goff[r]);
            cpa_commit();
        }

        // ---- S = Q K^T  (m16 x n64, k=64) ----
        float s[8][4];
        #pragma unroll
        for (int nf = 0; nf < 8; nf++)
            #pragma unroll
            for (int j = 0; j < 4; j++) s[nf][j] = 0.f;

        #pragma unroll
        for (int kf = 0; kf < 8; kf++) {
            #pragma unroll
            for (int nf = 0; nf < 8; nf++) {
                unsigned b0 = Ks[(nf * 8 + lq) * KS_W + kf * 8 + lr];
                unsigned b1 = Ks[(nf * 8 + lq) * KS_W + kf * 8 + 4 + lr];
                mma8(s[nf], aq[kf], b0, b1);
            }
        }
        __syncthreads();      // all warps done reading K

        // ---- issue K_{kb+1} (single buffer; covered by softmax+PV) ----
        if (kb < qi) {
            const float* ksrc = kg + (size_t)(kb + 1) * 64 * HD;
            #pragma unroll
            for (int r = 0; r < 8; r++) cpa16(kdst[r], ksrc + goff[r]);
            cpa_commit();
        }

        // ---- causal mask on diagonal block ----
        if (kb == qi) {
            int r0 = wm + lq, r1 = r0 + 8;
            #pragma unroll
            for (int nf = 0; nf < 8; nf++) {
                int cc = nf * 8 + 2 * lr;
                if (cc     > r0) s[nf][0] = -1e30f;
                if (cc + 1 > r0) s[nf][1] = -1e30f;
                if (cc     > r1) s[nf][2] = -1e30f;
                if (cc + 1 > r1) s[nf][3] = -1e30f;
            }
        }

        // ---- online softmax (rows wm+lq, wm+lq+8; quad reduce) ----
        float mx0 = -1e30f, mx1 = -1e30f;
        #pragma unroll
        for (int nf = 0; nf < 8; nf++) {
            mx0 = fmaxf(mx0, fmaxf(s[nf][0], s[nf][1]));
            mx1 = fmaxf(mx1, fmaxf(s[nf][2], s[nf][3]));
        }
        mx0 = fmaxf(mx0, __shfl_xor_sync(0xffffffffu, mx0, 1));
        mx0 = fmaxf(mx0, __shfl_xor_sync(0xffffffffu, mx0, 2));
        mx1 = fmaxf(mx1, __shfl_xor_sync(0xffffffffu, mx1, 1));
        mx1 = fmaxf(mx1, __shfl_xor_sync(0xffffffffu, mx1, 2));

        float mn0 = fmaxf(m0, mx0), mn1 = fmaxf(m1, mx1);
        float corr0 = __expf(m0 - mn0), corr1 = __expf(m1 - mn1);

        float sum0 = 0.f, sum1 = 0.f;
        #pragma unroll
        for (int nf = 0; nf < 8; nf++) {
            s[nf][0] = __expf(s[nf][0] - mn0);
            s[nf][1] = __expf(s[nf][1] - mn0);
            s[nf][2] = __expf(s[nf][2] - mn1);
            s[nf][3] = __expf(s[nf][3] - mn1);
            sum0 += s[nf][0] + s[nf][1];
            sum1 += s[nf][2] + s[nf][3];
        }
        sum0 += __shfl_xor_sync(0xffffffffu, sum0, 1);
        sum0 += __shfl_xor_sync(0xffffffffu, sum0, 2);
        sum1 += __shfl_xor_sync(0xffffffffu, sum1, 1);
        sum1 += __shfl_xor_sync(0xffffffffu, sum1, 2);

        l0 = l0 * corr0 + sum0;  m0 = mn0;
        l1 = l1 * corr1 + sum1;  m1 = mn1;

        #pragma unroll
        for (int nf = 0; nf < 8; nf++) {
            o[nf][0] *= corr0; o[nf][1] *= corr0;
            o[nf][2] *= corr1; o[nf][3] *= corr1;
        }

        // ---- P -> smem (warp-private rows), rebuild as A fragments ----
        #pragma unroll
        for (int nf = 0; nf < 8; nf++) {
            uint2 w0 = make_uint2(f2tf(s[nf][0]), f2tf(s[nf][1]));
            uint2 w1 = make_uint2(f2tf(s[nf][2]), f2tf(s[nf][3]));
            *(uint2*)&Ps[(wm + lq) * PS_W + nf * 8 + 2 * lr] = w0;
            *(uint2*)&Ps[(wm + lq + 8) * PS_W + nf * 8 + 2 * lr] = w1;
        }
        __syncwarp();

        // ---- O += P V  (m16 x n(d)=64, k=64 keys) ----
        #pragma unroll
        for (int kf = 0; kf < 8; kf++) {
            unsigned ap[4];
            ap[0] = Ps[(wm + lq) * PS_W + kf * 8 + lr];
            ap[1] = Ps[(wm + lq + 8) * PS_W + kf * 8 + lr];
            ap[2] = Ps[(wm + lq) * PS_W + kf * 8 + 4 + lr];
            ap[3] = Ps[(wm + lq + 8) * PS_W + kf * 8 + 4 + lr];
            #pragma unroll
            for (int nf = 0; nf < 8; nf++) {
                unsigned b0 = Vb[(kf * 8 + lr) * VS_W + nf * 8 + lq];
                unsigned b1 = Vb[(kf * 8 + 4 + lr) * VS_W + nf * 8 + lq];
                mma8(o[nf], ap, b0, b1);
            }
        }

        cpa_wait0();          // K_{kb+1}, V_{kb+1} landed
        __syncthreads();      // visible to all; V readers done before overwrite
    }

    // ---- normalize + write out ----
    float il0 = 1.f / l0, il1 = 1.f / l1;
    #pragma unroll
    for (int nf = 0; nf < 8; nf++) {
        int cc = nf * 8 + 2 * lr;
        *(float2*)&out[((size_t)b * SS + qi * 64 + wm + lq) * HD + cc] =
            make_float2(o[nf][0] * il0, o[nf][1] * il0);
        *(float2*)&out[((size_t)b * SS + qi * 64 + wm + lq + 8) * HD + cc] =
            make_float2(o[nf][2] * il1, o[nf][3] * il1);
    }
}

// ---------------------------------------------------------------------------
// kernel_launch
// ---------------------------------------------------------------------------
extern "C" void kernel_launch(void* const* d_in, const int* in_sizes, int n_in,
                              void* d_out, int out_size)
{
    const float* x  = (const float*)d_in[0];
    const float* Wq = (const float*)d_in[1];
    const float* Wk = (const float*)d_in[2];
    const float* Wv = (const float*)d_in[3];
    float* out = (float*)d_out;

    static int smem_set = 0;
    if (!smem_set) {
        cudaFuncSetAttribute(attn_kernel,
                             cudaFuncAttributeMaxDynamicSharedMemorySize,
                             SMEM_ATTN);
        smem_set = 1;
    }

    qkv_kernel<<<MM / 128, 256>>>(x, Wq, Wk, Wv);

    dim3 g2(64, BB);
    attn_kernel<<<g2, 128, SMEM_ATTN>>>(out);
}

// round 8
// speedup vs baseline: 4.6288x; 1.2769x over previous
#include <cuda_runtime.h>

// Problem constants
#define BB   4
#define SS   4096
#define DIN  768
#define HD   64
#define MM   (BB*SS)   // 16384 rows
#define NSPLIT 2
#define NQT  64        // q-tiles per batch
#define NPART (NQT * NSPLIT)   // 128 partials per batch

// Scratch (device globals: allocation-free; zero-initialized at load)
__device__ float g_q[MM * HD];
__device__ float g_k[MM * HD];
__device__ float g_v[MM * HD];
__device__ float g_po[BB * NPART * 64 * HD];   // unnormalized partial O
__device__ float g_pm[BB * NPART * 64];        // partial row max
__device__ float g_pl[BB * NPART * 64];        // partial row sum

// ---------------------------------------------------------------------------
// tf32 helpers
// ---------------------------------------------------------------------------
__device__ __forceinline__ unsigned f2tf(float f) {
    unsigned u;
    asm("cvt.rna.tf32.f32 %0, %1;" : "=r"(u) : "f"(f));
    return u;
}
__device__ __forceinline__ uint4 f2tf4(float4 v) {
    uint4 t;
    t.x = f2tf(v.x); t.y = f2tf(v.y); t.z = f2tf(v.z); t.w = f2tf(v.w);
    return t;
}
// D = A(m16 x k8, row) * B(k8 x n8, col) + D   (tf32 in, f32 accum)
__device__ __forceinline__ void mma8(float* c, const unsigned* a,
                                     unsigned b0, unsigned b1) {
    asm("mma.sync.aligned.m16n8k8.row.col.f32.tf32.tf32.f32 "
        "{%0,%1,%2,%3},{%4,%5,%6,%7},{%8,%9},{%0,%1,%2,%3};"
        : "+f"(c[0]), "+f"(c[1]), "+f"(c[2]), "+f"(c[3])
        : "r"(a[0]), "r"(a[1]), "r"(a[2]), "r"(a[3]), "r"(b0), "r"(b1));
}
__device__ __forceinline__ void cpa16(unsigned smem_dst, const void* gsrc) {
    asm volatile("cp.async.cg.shared.global [%0], [%1], 16;"
                 :: "r"(smem_dst), "l"(gsrc));
}
__device__ __forceinline__ void cpa_commit() {
    asm volatile("cp.async.commit_group;");
}
__device__ __forceinline__ void cpa_wait0() {
    asm volatile("cp.async.wait_group 0;");
}

// ---------------------------------------------------------------------------
// Kernel 1: fused QKV projection.  BM=64, N=192 fused.  grid = 256, block 256.
// 8 warps = 4(m) x 2(n); each warp m16 x n96 (12 n-frags). BK = 32.
// ---------------------------------------------------------------------------
__global__ __launch_bounds__(256) void qkv_kernel(
    const float* __restrict__ x,
    const float* __restrict__ Wq,
    const float* __restrict__ Wk,
    const float* __restrict__ Wv)
{
    __shared__ unsigned Xs[64][36];     // [m][k] tf32
    __shared__ unsigned Ws[32][200];    // [k][n=192] tf32

    const int tid  = threadIdx.x;
    const int lane = tid & 31;
    const int warp = tid >> 5;
    const int lq = lane >> 2;
    const int lr = lane & 3;
    const int wm = (warp >> 1) * 16;    // 0,16,32,48
    const int wn = (warp & 1) * 96;     // 0,96
    const int m0 = blockIdx.x * 64;

    float c[12][4];
    #pragma unroll
    for (int nf = 0; nf < 12; nf++)
        #pragma unroll
        for (int j = 0; j < 4; j++) c[nf][j] = 0.f;

    float4 xreg[2], wreg[6];

    #pragma unroll
    for (int r = 0; r < 2; r++) {
        int idx = tid + r * 256;              // 0..511
        int row = idx >> 3, c4 = (idx & 7) * 4;
        xreg[r] = *(const float4*)&x[(size_t)(m0 + row) * DIN + c4];
    }
    #pragma unroll
    for (int r = 0; r < 6; r++) {
        int idx = tid + r * 256;
        int wsel = idx >> 9;
        int j = idx & 511;
        int row = j >> 4, c4 = (j & 15) * 4;
        const float* W = (wsel == 0) ? Wq : (wsel == 1) ? Wk : Wv;
        wreg[r] = *(const float4*)&W[(size_t)row * HD + c4];
    }

    for (int k0 = 0; k0 < DIN; k0 += 32) {
        #pragma unroll
        for (int r = 0; r < 2; r++) {
            int idx = tid + r * 256;
            int row = idx >> 3, c4 = (idx & 7) * 4;
            *(uint4*)&Xs[row][c4] = f2tf4(xreg[r]);
        }
        #pragma unroll
        for (int r = 0; r < 6; r++) {
            int idx = tid + r * 256;
            int wsel = idx >> 9;
            int j = idx & 511;
            int row = j >> 4, c4 = (j & 15) * 4;
            *(uint4*)&Ws[row][wsel * 64 + c4] = f2tf4(wreg[r]);
        }
        __syncthreads();

        if (k0 + 32 < DIN) {
            #pragma unroll
            for (int r = 0; r < 2; r++) {
                int idx = tid + r * 256;
                int row = idx >> 3, c4 = (idx & 7) * 4;
                xreg[r] = *(const float4*)&x[(size_t)(m0 + row) * DIN + k0 + 32 + c4];
            }
            #pragma unroll
            for (int r = 0; r < 6; r++) {
                int idx = tid + r * 256;
                int wsel = idx >> 9;
                int j = idx & 511;
                int row = j >> 4, c4 = (j & 15) * 4;
                const float* W = (wsel == 0) ? Wq : (wsel == 1) ? Wk : Wv;
                wreg[r] = *(const float4*)&W[(size_t)(k0 + 32 + row) * HD + c4];
            }
        }

        #pragma unroll
        for (int kf = 0; kf < 4; kf++) {
            unsigned a[4];
            a[0] = Xs[wm + lq][kf * 8 + lr];
            a[1] = Xs[wm + lq + 8][kf * 8 + lr];
            a[2] = Xs[wm + lq][kf * 8 + 4 + lr];
            a[3] = Xs[wm + lq + 8][kf * 8 + 4 + lr];
            #pragma unroll
            for (int nf = 0; nf < 12; nf++) {
                unsigned b0 = Ws[kf * 8 + lr][wn + nf * 8 + lq];
                unsigned b1 = Ws[kf * 8 + 4 + lr][wn + nf * 8 + lq];
                mma8(c[nf], a, b0, b1);
            }
        }
        __syncthreads();
    }

    #pragma unroll
    for (int nf = 0; nf < 12; nf++) {
        int gcol = wn + nf * 8;
        int which = gcol >> 6;
        int nc = (gcol & 63) + 2 * lr;
        float* outp = (which == 0) ? g_q : (which == 1) ? g_k : g_v;
        *(float2*)&outp[(size_t)(m0 + wm + lq) * HD + nc] =
            make_float2(c[nf][0], c[nf][1]);
        *(float2*)&outp[(size_t)(m0 + wm + lq + 8) * HD + nc] =
            make_float2(c[nf][2], c[nf][3]);
    }
}

// ---------------------------------------------------------------------------
// Kernel 2: causal flash attention, tf32 mma + cp.async, SPLIT-K (2 splits).
// grid = (128, B): qs -> idx = qs>>1 (q-tile 63-idx, big first), split = qs&1.
// Each CTA: 4 warps, BM=64, keys [lo,hi) of its q-tile; writes unnormalized
// partial O + (m,l) stats.  3 CTAs/SM.
// ---------------------------------------------------------------------------
#define KS_W 68
#define VS_W 72
#define PS_W 68
#define KS_SZ (64 * KS_W)
#define VS_SZ (64 * VS_W)
#define SMEM_ATTN ((KS_SZ + 2 * VS_SZ + 64 * PS_W) * (int)sizeof(unsigned))

__global__ __launch_bounds__(128, 3) void attn_kernel()
{
    extern __shared__ unsigned smu[];
    unsigned* Ks = smu;                      // [64][68]
    unsigned* Vs = smu + KS_SZ;              // [2][64][72]
    unsigned* Ps = smu + KS_SZ + 2 * VS_SZ;  // [64][68]

    const int b     = blockIdx.y;
    const int qs    = blockIdx.x;            // 0..127
    const int idx   = qs >> 1;
    const int split = qs & 1;
    const int qi    = 63 - idx;              // big tiles first
    const int nb    = qi + 1;
    const int half  = (nb + 1) >> 1;
    const int lo    = split ? half : 0;
    const int hi    = split ? nb : half;

    const int tid  = threadIdx.x;
    const int lane = tid & 31;
    const int warp = tid >> 5;
    const int lq = lane >> 2;
    const int lr = lane & 3;
    const int wm = warp * 16;

    const size_t pbase = ((size_t)b * NPART + qs) * 64;

    if (lo >= hi) {                          // empty split (qi=0, split=1)
        if (tid < 64) {
            g_pm[pbase + tid] = -1e30f;
            g_pl[pbase + tid] = 0.f;
        }
        return;                              // po region stays zero (unused)
    }

    const float* __restrict__ qb = g_q + ((size_t)b * SS + qi * 64) * HD;
    const float* __restrict__ kg = g_k + (size_t)b * SS * HD;
    const float* __restrict__ vg = g_v + (size_t)b * SS * HD;

    unsigned kdst[8], vdst0[8], vdst1[8];
    size_t goff[8];
    #pragma unroll
    for (int r = 0; r < 8; r++) {
        int i2 = tid + r * 128;
        int row = i2 >> 4, c4 = (i2 & 15) * 4;
        kdst[r]  = (unsigned)__cvta_generic_to_shared(&Ks[row * KS_W + c4]);
        vdst0[r] = (unsigned)__cvta_generic_to_shared(&Vs[row * VS_W + c4]);
        vdst1[r] = (unsigned)__cvta_generic_to_shared(&Vs[VS_SZ + row * VS_W + c4]);
        goff[r]  = (size_t)row * HD + c4;
    }

    // ---- issue K[lo], V[lo] ----
    {
        const float* ks0 = kg + (size_t)lo * 64 * HD;
        const float* vs0 = vg + (size_t)lo * 64 * HD;
        #pragma unroll
        for (int r = 0; r < 8; r++) {
            cpa16(kdst[r],  ks0 + goff[r]);
            cpa16(vdst0[r], vs0 + goff[r]);
        }
        cpa_commit();
    }

    // ---- stage Q (scaled 1/8, tf32) through Ps, build A fragments ----
    #pragma unroll
    for (int r = 0; r < 8; r++) {
        int i2 = tid + r * 128;
        int row = i2 >> 4, c4 = (i2 & 15) * 4;
        float4 v = *(const float4*)&qb[(size_t)row * HD + c4];
        uint4 t;
        t.x = f2tf(v.x * 0.125f); t.y = f2tf(v.y * 0.125f);
        t.z = f2tf(v.z * 0.125f); t.w = f2tf(v.w * 0.125f);
        *(uint4*)&Ps[row * PS_W + c4] = t;
    }
    __syncthreads();

    unsigned aq[8][4];
    #pragma unroll
    for (int kf = 0; kf < 8; kf++) {
        aq[kf][0] = Ps[(wm + lq) * PS_W + kf * 8 + lr];
        aq[kf][1] = Ps[(wm + lq + 8) * PS_W + kf * 8 + lr];
        aq[kf][2] = Ps[(wm + lq) * PS_W + kf * 8 + 4 + lr];
        aq[kf][3] = Ps[(wm + lq + 8) * PS_W + kf * 8 + 4 + lr];
    }

    float m0 = -1e30f, m1 = -1e30f, l0 = 0.f, l1 = 0.f;
    float o[8][4];
    #pragma unroll
    for (int nf = 0; nf < 8; nf++)
        #pragma unroll
        for (int j = 0; j < 4; j++) o[nf][j] = 0.f;

    cpa_wait0();
    __syncthreads();

    for (int kb = lo; kb < hi; kb++) {
        const int par = (kb - lo) & 1;
        unsigned* Vb = Vs + par * VS_SZ;

        // issue V_{kb+1}
        if (kb + 1 < hi) {
            const float* vsrc = vg + (size_t)(kb + 1) * 64 * HD;
            unsigned* vd = par ? vdst0 : vdst1;
            #pragma unroll
            for (int r = 0; r < 8; r++) cpa16(vd[r], vsrc + goff[r]);
            cpa_commit();
        }

        // ---- S = Q K^T ----
        float s[8][4];
        #pragma unroll
        for (int nf = 0; nf < 8; nf++)
            #pragma unroll
            for (int j = 0; j < 4; j++) s[nf][j] = 0.f;

        #pragma unroll
        for (int kf = 0; kf < 8; kf++) {
            #pragma unroll
            for (int nf = 0; nf < 8; nf++) {
                unsigned b0 = Ks[(nf * 8 + lq) * KS_W + kf * 8 + lr];
                unsigned b1 = Ks[(nf * 8 + lq) * KS_W + kf * 8 + 4 + lr];
                mma8(s[nf], aq[kf], b0, b1);
            }
        }
        __syncthreads();

        // issue K_{kb+1}
        if (kb + 1 < hi) {
            const float* ksrc = kg + (size_t)(kb + 1) * 64 * HD;
            #pragma unroll
            for (int r = 0; r < 8; r++) cpa16(kdst[r], ksrc + goff[r]);
            cpa_commit();
        }

        // causal mask on diagonal block
        if (kb == qi) {
            int r0 = wm + lq, r1 = r0 + 8;
            #pragma unroll
            for (int nf = 0; nf < 8; nf++) {
                int cc = nf * 8 + 2 * lr;
                if (cc     > r0) s[nf][0] = -1e30f;
                if (cc + 1 > r0) s[nf][1] = -1e30f;
                if (cc     > r1) s[nf][2] = -1e30f;
                if (cc + 1 > r1) s[nf][3] = -1e30f;
            }
        }

        // ---- online softmax ----
        float mx0 = -1e30f, mx1 = -1e30f;
        #pragma unroll
        for (int nf = 0; nf < 8; nf++) {
            mx0 = fmaxf(mx0, fmaxf(s[nf][0], s[nf][1]));
            mx1 = fmaxf(mx1, fmaxf(s[nf][2], s[nf][3]));
        }
        mx0 = fmaxf(mx0, __shfl_xor_sync(0xffffffffu, mx0, 1));
        mx0 = fmaxf(mx0, __shfl_xor_sync(0xffffffffu, mx0, 2));
        mx1 = fmaxf(mx1, __shfl_xor_sync(0xffffffffu, mx1, 1));
        mx1 = fmaxf(mx1, __shfl_xor_sync(0xffffffffu, mx1, 2));

        float mn0 = fmaxf(m0, mx0), mn1 = fmaxf(m1, mx1);
        float corr0 = __expf(m0 - mn0), corr1 = __expf(m1 - mn1);

        float sum0 = 0.f, sum1 = 0.f;
        #pragma unroll
        for (int nf = 0; nf < 8; nf++) {
            s[nf][0] = __expf(s[nf][0] - mn0);
            s[nf][1] = __expf(s[nf][1] - mn0);
            s[nf][2] = __expf(s[nf][2] - mn1);
            s[nf][3] = __expf(s[nf][3] - mn1);
            sum0 += s[nf][0] + s[nf][1];
            sum1 += s[nf][2] + s[nf][3];
        }
        sum0 += __shfl_xor_sync(0xffffffffu, sum0, 1);
        sum0 += __shfl_xor_sync(0xffffffffu, sum0, 2);
        sum1 += __shfl_xor_sync(0xffffffffu, sum1, 1);
        sum1 += __shfl_xor_sync(0xffffffffu, sum1, 2);

        l0 = l0 * corr0 + sum0;  m0 = mn0;
        l1 = l1 * corr1 + sum1;  m1 = mn1;

        #pragma unroll
        for (int nf = 0; nf < 8; nf++) {
            o[nf][0] *= corr0; o[nf][1] *= corr0;
            o[nf][2] *= corr1; o[nf][3] *= corr1;
        }

        // ---- P -> smem (warp-private), rebuild as A fragments ----
        #pragma unroll
        for (int nf = 0; nf < 8; nf++) {
            uint2 w0 = make_uint2(f2tf(s[nf][0]), f2tf(s[nf][1]));
            uint2 w1 = make_uint2(f2tf(s[nf][2]), f2tf(s[nf][3]));
            *(uint2*)&Ps[(wm + lq) * PS_W + nf * 8 + 2 * lr] = w0;
            *(uint2*)&Ps[(wm + lq + 8) * PS_W + nf * 8 + 2 * lr] = w1;
        }
        __syncwarp();

        // ---- O += P V ----
        #pragma unroll
        for (int kf = 0; kf < 8; kf++) {
            unsigned ap[4];
            ap[0] = Ps[(wm + lq) * PS_W + kf * 8 + lr];
            ap[1] = Ps[(wm + lq + 8) * PS_W + kf * 8 + lr];
            ap[2] = Ps[(wm + lq) * PS_W + kf * 8 + 4 + lr];
            ap[3] = Ps[(wm + lq + 8) * PS_W + kf * 8 + 4 + lr];
            #pragma unroll
            for (int nf = 0; nf < 8; nf++) {
                unsigned b0 = Vb[(kf * 8 + lr) * VS_W + nf * 8 + lq];
                unsigned b1 = Vb[(kf * 8 + 4 + lr) * VS_W + nf * 8 + lq];
                mma8(o[nf], ap, b0, b1);
            }
        }

        cpa_wait0();
        __syncthreads();
    }

    // ---- write partials (unnormalized O, m, l) ----
    #pragma unroll
    for (int nf = 0; nf < 8; nf++) {
        int cc = nf * 8 + 2 * lr;
        *(float2*)&g_po[(pbase + wm + lq) * HD + cc] =
            make_float2(o[nf][0], o[nf][1]);
        *(float2*)&g_po[(pbase + wm + lq + 8) * HD + cc] =
            make_float2(o[nf][2], o[nf][3]);
    }
    if (lr == 0) {
        g_pm[pbase + wm + lq]     = m0;
        g_pl[pbase + wm + lq]     = l0;
        g_pm[pbase + wm + lq + 8] = m1;
        g_pl[pbase + wm + lq + 8] = l1;
    }
}

// ---------------------------------------------------------------------------
// Kernel 3: merge the 2 splits per q-tile.
// grid = (64, B), block 256: thread handles (row = tid>>2, 16 cols).
// ---------------------------------------------------------------------------
__global__ __launch_bounds__(256) void merge_kernel(float* __restrict__ out)
{
    const int b   = blockIdx.y;
    const int idx = blockIdx.x;          // matches attn ordering
    const int qi  = 63 - idx;
    const int tid = threadIdx.x;
    const int row = tid >> 2;
    const int c16 = (tid & 3) * 16;

    const size_t p0 = ((size_t)b * NPART + 2 * idx) * 64;
    const size_t p1 = p0 + 64;

    float m0 = g_pm[p0 + row], l0 = g_pl[p0 + row];
    float m1 = g_pm[p1 + row], l1 = g_pl[p1 + row];
    float M  = fmaxf(m0, m1);
    float w0 = __expf(m0 - M);
    float w1 = (l1 > 0.f) ? __expf(m1 - M) : 0.f;
    float inv = 1.0f / (l0 * w0 + l1 * w1);
    w0 *= inv; w1 *= inv;

    const float* po0 = g_po + (p0 + row) * HD + c16;
    const float* po1 = g_po + (p1 + row) * HD + c16;
    float* op = out + ((size_t)b * SS + qi * 64 + row) * HD + c16;

    #pragma unroll
    for (int j = 0; j < 16; j += 4) {
        float4 a = *(const float4*)&po0[j];
        float4 c = *(const float4*)&po1[j];
        *(float4*)&op[j] = make_float4(a.x * w0 + c.x * w1,
                                       a.y * w0 + c.y * w1,
                                       a.z * w0 + c.z * w1,
                                       a.w * w0 + c.w * w1);
    }
}

// ---------------------------------------------------------------------------
// kernel_launch
// ---------------------------------------------------------------------------
extern "C" void kernel_launch(void* const* d_in, const int* in_sizes, int n_in,
                              void* d_out, int out_size)
{
    const float* x  = (const float*)d_in[0];
    const float* Wq = (const float*)d_in[1];
    const float* Wk = (const float*)d_in[2];
    const float* Wv = (const float*)d_in[3];
    float* out = (float*)d_out;

    static int smem_set = 0;
    if (!smem_set) {
        cudaFuncSetAttribute(attn_kernel,
                             cudaFuncAttributeMaxDynamicSharedMemorySize,
                             SMEM_ATTN);
        smem_set = 1;
    }

    qkv_kernel<<<MM / 64, 256>>>(x, Wq, Wk, Wv);

    dim3 g2(NQT * NSPLIT, BB);
    attn_kernel<<<g2, 128, SMEM_ATTN>>>();

    dim3 g3(NQT, BB);
    merge_kernel<<<g3, 256>>>(out);
}